// round 1
// baseline (speedup 1.0000x reference)
#include <cuda_runtime.h>
#include <cstdint>

// Problem constants
#define NN 8
#define CC 64
#define FF 256
#define TT 256
#define BB (NN*TT)          // 2048 batches
#define RS 68               // smem row stride in floats (16B-aligned, conflict-free)

typedef unsigned long long u64;

// 128MB scratch: holds xT [B,F,C] then (in-place, per-CTA safe) y [B,F,C]
__device__ float g_scratch[(size_t)BB * FF * CC];

// ---------------- packed fp32x2 helpers (full fp32 precision, 2x throughput) ----------
static __device__ __forceinline__ u64 pk2(float lo, float hi) {
    u64 r; asm("mov.b64 %0,{%1,%2};" : "=l"(r) : "f"(lo), "f"(hi)); return r;
}
static __device__ __forceinline__ void upk2(u64 a, float& lo, float& hi) {
    asm("mov.b64 {%0,%1},%2;" : "=f"(lo), "=f"(hi) : "l"(a));
}
static __device__ __forceinline__ u64 f2fma(u64 a, u64 b, u64 c) {
    u64 d; asm("fma.rn.f32x2 %0,%1,%2,%3;" : "=l"(d) : "l"(a), "l"(b), "l"(c)); return d;
}
static __device__ __forceinline__ u64 f2mul(u64 a, u64 b) {
    u64 d; asm("mul.rn.f32x2 %0,%1,%2;" : "=l"(d) : "l"(a), "l"(b)); return d;
}
static __device__ __forceinline__ u64 f2add(u64 a, u64 b) {
    u64 d; asm("add.rn.f32x2 %0,%1,%2;" : "=l"(d) : "l"(a), "l"(b)); return d;
}

// ---------------- kernel 1: transpose [N,C,F,T] -> xT [N*T, F, C] ----------------
// grid (T/32, C/32, N*F), block (32,8)
__global__ void k_tin(const float* __restrict__ in) {
    __shared__ float tile[32][33];
    int n = blockIdx.z >> 8, f = blockIdx.z & 255;
    int c0 = blockIdx.y << 5, t0 = blockIdx.x << 5;
    int tx = threadIdx.x, ty = threadIdx.y;
    int base_in = ((n * 64) * 256 + f) * 256;          // + c*65536 + t
#pragma unroll
    for (int i = 0; i < 32; i += 8) {
        tile[ty + i][tx] = in[base_in + (c0 + ty + i) * 65536 + t0 + tx];
    }
    __syncthreads();
    int base_out = n * (256 * 16384) + f * 64;          // + t*16384 + c
#pragma unroll
    for (int i = 0; i < 32; i += 8) {
        g_scratch[base_out + (t0 + ty + i) * 16384 + c0 + tx] = tile[tx][ty + i];
    }
}

// ---------------- kernel 3: y [B,F,C] -> out [N,C,F,T] (+ residual) ----------------
__global__ void k_tout(const float* __restrict__ in, float* __restrict__ out) {
    __shared__ float tile[32][33];
    int n = blockIdx.z >> 8, f = blockIdx.z & 255;
    int c0 = blockIdx.y << 5, t0 = blockIdx.x << 5;
    int tx = threadIdx.x, ty = threadIdx.y;
    int base_y = n * (256 * 16384) + f * 64;
#pragma unroll
    for (int i = 0; i < 32; i += 8) {
        tile[ty + i][tx] = g_scratch[base_y + (t0 + ty + i) * 16384 + c0 + tx];
    }
    __syncthreads();
    int base_o = ((n * 64) * 256 + f) * 256;
#pragma unroll
    for (int i = 0; i < 32; i += 8) {
        int a = base_o + (c0 + ty + i) * 65536 + t0 + tx;
        out[a] = tile[tx][ty + i] + in[a];
    }
}

// ---------------- fused attention kernel ----------------
// smem layout (floats)
#define OFF_K   (256 * RS)            // 17408
#define OFF_V   (2 * 256 * RS)        // 34816
#define OFF_W   (3 * 256 * RS)        // 52224
#define OFF_G1  (OFF_W + 64 * RS)     // 56576
#define OFF_B1  (OFF_G1 + 64)
#define OFF_G2  (OFF_B1 + 64)
#define OFF_B2  (OFF_G2 + 64)
#define OFF_G3  (OFF_B2 + 64)
#define OFF_B3  (OFF_G3 + 64)
#define OFF_BIAS (OFF_B3 + 64)
#define SMEM_FLOATS (OFF_BIAS + 64)   // 57024
#define SMEM_BYTES  (SMEM_FLOATS * 4) // 228096 < 227KB limit

// stage a 64x64 weight (row-major [out][in]) + bias into smem; caller syncs
static __device__ __forceinline__ void stageW(const float* __restrict__ W,
                                              const float* __restrict__ bias,
                                              float* sw, float* sbias, int tid) {
    for (int i = tid; i < 4096; i += 256) sw[(i >> 6) * RS + (i & 63)] = W[i];
    if (tid < 64) sbias[tid] = bias[tid];
}

// per-thread row GEMM: dst[o] = bias[o] + sum_i h2[i] * W[o][i], o=0..63
static __device__ __forceinline__ void gemm64(const u64* h2, const float* sw,
                                              const float* sbias, float* dst) {
    for (int o = 0; o < 64; o += 4) {
        const ulonglong2* w0 = (const ulonglong2*)(sw + (o + 0) * RS);
        const ulonglong2* w1 = (const ulonglong2*)(sw + (o + 1) * RS);
        const ulonglong2* w2 = (const ulonglong2*)(sw + (o + 2) * RS);
        const ulonglong2* w3 = (const ulonglong2*)(sw + (o + 3) * RS);
        u64 a0 = 0ull, a1 = 0ull, a2 = 0ull, a3 = 0ull;
#pragma unroll
        for (int j = 0; j < 16; j++) {
            ulonglong2 x0 = w0[j], x1 = w1[j], x2 = w2[j], x3 = w3[j];
            u64 hlo = h2[2 * j], hhi = h2[2 * j + 1];
            a0 = f2fma(hlo, x0.x, a0); a1 = f2fma(hlo, x1.x, a1);
            a2 = f2fma(hlo, x2.x, a2); a3 = f2fma(hlo, x3.x, a3);
            a0 = f2fma(hhi, x0.y, a0); a1 = f2fma(hhi, x1.y, a1);
            a2 = f2fma(hhi, x2.y, a2); a3 = f2fma(hhi, x3.y, a3);
        }
        float e0, e1, e2, e3, e4, e5, e6, e7;
        upk2(a0, e0, e1); upk2(a1, e2, e3); upk2(a2, e4, e5); upk2(a3, e6, e7);
        float4 r = make_float4(e0 + e1 + sbias[o],     e2 + e3 + sbias[o + 1],
                               e4 + e5 + sbias[o + 2], e6 + e7 + sbias[o + 3]);
        *reinterpret_cast<float4*>(dst + o) = r;
    }
}

__global__ void __launch_bounds__(256, 1) k_attn(
    const float* __restrict__ Wq, const float* __restrict__ bq,
    const float* __restrict__ Wk, const float* __restrict__ bk,
    const float* __restrict__ Wv, const float* __restrict__ bv,
    const float* __restrict__ g1, const float* __restrict__ b1,
    const float* __restrict__ g2, const float* __restrict__ b2,
    const float* __restrict__ Wt, const float* __restrict__ bt,
    const float* __restrict__ g3, const float* __restrict__ b3,
    const float* __restrict__ alpha)
{
    extern __shared__ float sm[];
    float* sh    = sm;
    float* sk    = sm + OFF_K;
    float* sv    = sm + OFF_V;
    float* sw    = sm + OFF_W;
    float* sg1   = sm + OFF_G1;
    float* sb1   = sm + OFF_B1;
    float* sg2   = sm + OFF_G2;
    float* sb2   = sm + OFF_B2;
    float* sg3   = sm + OFF_G3;
    float* sb3   = sm + OFF_B3;
    float* sbias = sm + OFF_BIAS;

    int tid = threadIdx.x;
    int b = blockIdx.x;
    float* xb = g_scratch + b * 16384;
    float al = __ldg(alpha);

    // ---- Phase A: load x tile + params
    for (int i = tid; i < 16384; i += 256) sh[(i >> 6) * RS + (i & 63)] = xb[i];
    if (tid < 64) {
        sg1[tid] = g1[tid]; sb1[tid] = b1[tid];
        sg2[tid] = g2[tid]; sb2[tid] = b2[tid];
        sg3[tid] = g3[tid]; sb3[tid] = b3[tid];
    }
    __syncthreads();

    // ---- Phase B: LayerNorm1 over C (warp per row, rows strided by 8)
    int lane = tid & 31, wid = tid >> 5;
    {
        float gl0 = sg1[lane], bl0 = sb1[lane], gl1 = sg1[lane + 32], bl1 = sb1[lane + 32];
        for (int r = wid; r < 256; r += 8) {
            float a0 = sh[r * RS + lane], a1 = sh[r * RS + 32 + lane];
            float s = a0 + a1;
#pragma unroll
            for (int o = 16; o; o >>= 1) s += __shfl_xor_sync(0xffffffffu, s, o);
            float mean = s * (1.0f / 64.0f);
            float d0 = a0 - mean, d1 = a1 - mean;
            float qv = d0 * d0 + d1 * d1;
#pragma unroll
            for (int o = 16; o; o >>= 1) qv += __shfl_xor_sync(0xffffffffu, qv, o);
            float rstd = rsqrtf(qv * (1.0f / 64.0f) + 1e-5f);
            sh[r * RS + lane]      = d0 * rstd * gl0 + bl0;
            sh[r * RS + 32 + lane] = d1 * rstd * gl1 + bl1;
        }
    }
    __syncthreads();

    // ---- load this thread's normalized row into registers (packed)
    u64 hr[32];
    {
        const ulonglong2* hp = (const ulonglong2*)(sh + tid * RS);
#pragma unroll
        for (int j = 0; j < 16; j++) { ulonglong2 t = hp[j]; hr[2 * j] = t.x; hr[2 * j + 1] = t.y; }
    }

    // ---- Phase C: K, V, Q GEMMs (weight buffer reused with syncs)
    stageW(Wk, bk, sw, sbias, tid); __syncthreads();
    gemm64(hr, sw, sbias, sk + tid * RS); __syncthreads();

    stageW(Wv, bv, sw, sbias, tid); __syncthreads();
    gemm64(hr, sw, sbias, sv + tid * RS); __syncthreads();

    stageW(Wq, bq, sw, sbias, tid); __syncthreads();
    gemm64(hr, sw, sbias, sh + tid * RS);   // q into own (now free) h row
    u64 q2[32];
    {
        const ulonglong2* qp = (const ulonglong2*)(sh + tid * RS);
#pragma unroll
        for (int j = 0; j < 16; j++) { ulonglong2 t = qp[j]; q2[2 * j] = t.x; q2[2 * j + 1] = t.y; }
    }
    __syncthreads();

    // stage Wt/bt now (attention doesn't touch sw/sbias)
    stageW(Wt, bt, sw, sbias, tid); __syncthreads();

    // ---- Phase D: attention row (online softmax with lazy rescale)
    u64 acc[32];
#pragma unroll
    for (int j = 0; j < 32; j++) acc[j] = 0ull;
    float m = -1e30f, l = 0.0f;

#pragma unroll 2
    for (int s = 0; s < 256; s++) {
        const ulonglong2* kp = (const ulonglong2*)(sk + s * RS);
        u64 dA = 0ull, dB = 0ull, dC = 0ull, dD = 0ull;
#pragma unroll
        for (int j = 0; j < 16; j += 4) {
            ulonglong2 k0 = kp[j], k1 = kp[j + 1], k2 = kp[j + 2], k3 = kp[j + 3];
            dA = f2fma(q2[2 * j],     k0.x, dA); dB = f2fma(q2[2 * j + 2], k1.x, dB);
            dC = f2fma(q2[2 * j + 4], k2.x, dC); dD = f2fma(q2[2 * j + 6], k3.x, dD);
            dA = f2fma(q2[2 * j + 1], k0.y, dA); dB = f2fma(q2[2 * j + 3], k1.y, dB);
            dC = f2fma(q2[2 * j + 5], k2.y, dC); dD = f2fma(q2[2 * j + 7], k3.y, dD);
        }
        u64 dS = f2add(f2add(dA, dB), f2add(dC, dD));
        float dl, dh; upk2(dS, dl, dh);
        float sc = (dl + dh) * 0.125f;

        if (sc > m) {                       // rare after warm-up (~ln(256) times)
            float corr = __expf(m - sc);    // m=-1e30 first time -> corr=0
            l *= corr;
            u64 c2 = pk2(corr, corr);
#pragma unroll
            for (int j = 0; j < 32; j++) acc[j] = f2mul(acc[j], c2);
            m = sc;
        }
        float p = __expf(sc - m);
        l += p;
        u64 p2 = pk2(p, p);
        const ulonglong2* vp = (const ulonglong2*)(sv + s * RS);
#pragma unroll
        for (int j = 0; j < 16; j++) {
            ulonglong2 vv = vp[j];
            acc[2 * j]     = f2fma(p2, vv.x, acc[2 * j]);
            acc[2 * j + 1] = f2fma(p2, vv.y, acc[2 * j + 1]);
        }
    }

    // ---- Phase E: normalize + LayerNorm2 over H (thread-local)
    float wvv[64];
    {
        float inv = 1.0f / l;
#pragma unroll
        for (int j = 0; j < 32; j++) {
            float lo, hi; upk2(acc[j], lo, hi);
            wvv[2 * j] = lo * inv; wvv[2 * j + 1] = hi * inv;
        }
        float s2 = 0.0f;
#pragma unroll
        for (int i = 0; i < 64; i++) s2 += wvv[i];
        float mean = s2 * (1.0f / 64.0f);
        float vs = 0.0f;
#pragma unroll
        for (int i = 0; i < 64; i++) { float d = wvv[i] - mean; vs += d * d; }
        float rstd = rsqrtf(vs * (1.0f / 64.0f) + 1e-5f);
#pragma unroll
        for (int j = 0; j < 32; j++) {
            float v0 = (wvv[2 * j]     - mean) * rstd * sg2[2 * j]     + sb2[2 * j];
            float v1 = (wvv[2 * j + 1] - mean) * rstd * sg2[2 * j + 1] + sb2[2 * j + 1];
            acc[j] = pk2(v0, v1);           // reuse acc as packed LN2 output
        }
    }

    // ---- Phase F: output GEMM (Wt), then LN3 + PReLU, write back
    gemm64(acc, sw, sbias, sh + tid * RS);
    {
        const float4* op = (const float4*)(sh + tid * RS);
        float ov[64];
#pragma unroll
        for (int j = 0; j < 16; j++) {
            float4 t4 = op[j];
            ov[4 * j] = t4.x; ov[4 * j + 1] = t4.y; ov[4 * j + 2] = t4.z; ov[4 * j + 3] = t4.w;
        }
        float s3 = 0.0f;
#pragma unroll
        for (int i = 0; i < 64; i++) s3 += ov[i];
        float mean = s3 * (1.0f / 64.0f);
        float vs = 0.0f;
#pragma unroll
        for (int i = 0; i < 64; i++) { float d = ov[i] - mean; vs += d * d; }
        float rstd = rsqrtf(vs * (1.0f / 64.0f) + 1e-5f);
        float4* opw = (float4*)(sh + tid * RS);
#pragma unroll
        for (int j = 0; j < 16; j++) {
            float4 r;
            float e;
            e = (ov[4 * j]     - mean) * rstd * sg3[4 * j]     + sb3[4 * j];     r.x = (e >= 0.0f) ? e : al * e;
            e = (ov[4 * j + 1] - mean) * rstd * sg3[4 * j + 1] + sb3[4 * j + 1]; r.y = (e >= 0.0f) ? e : al * e;
            e = (ov[4 * j + 2] - mean) * rstd * sg3[4 * j + 2] + sb3[4 * j + 2]; r.z = (e >= 0.0f) ? e : al * e;
            e = (ov[4 * j + 3] - mean) * rstd * sg3[4 * j + 3] + sb3[4 * j + 3]; r.w = (e >= 0.0f) ? e : al * e;
            opw[j] = r;
        }
    }
    __syncthreads();
    // coalesced write-back into the scratch (same region this CTA read in Phase A)
    for (int i = tid; i < 16384; i += 256) xb[i] = sh[(i >> 6) * RS + (i & 63)];
}

// ---------------- launch ----------------
extern "C" void kernel_launch(void* const* d_in, const int* in_sizes, int n_in,
                              void* d_out, int out_size) {
    (void)in_sizes; (void)n_in; (void)out_size;
    const float* inputs = (const float*)d_in[0];
    const float* Wq = (const float*)d_in[1];
    const float* bq = (const float*)d_in[2];
    const float* Wk = (const float*)d_in[3];
    const float* bk = (const float*)d_in[4];
    const float* Wv = (const float*)d_in[5];
    const float* bv = (const float*)d_in[6];
    const float* g1 = (const float*)d_in[7];
    const float* b1 = (const float*)d_in[8];
    const float* g2 = (const float*)d_in[9];
    const float* b2 = (const float*)d_in[10];
    const float* Wt = (const float*)d_in[11];
    const float* bt = (const float*)d_in[12];
    const float* g3 = (const float*)d_in[13];
    const float* b3 = (const float*)d_in[14];
    const float* alpha = (const float*)d_in[15];
    float* out = (float*)d_out;

    cudaFuncSetAttribute(k_attn, cudaFuncAttributeMaxDynamicSharedMemorySize, SMEM_BYTES);

    dim3 tgrid(8, 2, NN * FF);   // (T/32, C/32, N*F)
    dim3 tblk(32, 8);
    k_tin<<<tgrid, tblk>>>(inputs);
    k_attn<<<BB, 256, SMEM_BYTES>>>(Wq, bq, Wk, bk, Wv, bv, g1, b1, g2, b2,
                                    Wt, bt, g3, b3, alpha);
    k_tout<<<tgrid, tblk>>>(inputs, out);
}